// round 1
// baseline (speedup 1.0000x reference)
#include <cuda_runtime.h>
#include <math.h>

// ---------------- problem constants (fixed by the dataset) ----------------
#define NN     87381          // total nodes = (4^9-1)/3
#define HH     512            // hidden
#define OUTF   256            // output features
#define NLEAF  65536          // 4^8 leaves
#define SLEAF  21845          // LEVEL_STARTS[8]
// LEVEL_STARTS[d] = (4^d - 1)/3
static const int LS[10] = {0,1,5,21,85,341,1365,5461,21845,87381};

// ---------------- scratch (static device globals; no allocation) ----------
__device__ float g_h0  [(size_t)NN * HH];       // layer input / final h (ping)
__device__ float g_hid [(size_t)NN * HH];       // hidden (pong)
__device__ float g_cell[(size_t)NN * HH];       // cell state
__device__ float g_iou [(size_t)NLEAF * 1536];  // iou buffer (max = leaf level)
__device__ float g_hsum[(size_t)16384 * HH];    // child hidden sum
__device__ float g_fx  [(size_t)16384 * HH];    // x @ W_fx
__device__ float g_fh  [(size_t)NLEAF * HH];    // children @ W_fh (max 4*16384 rows)
__device__ float g_part[(size_t)512 * HH];      // column-sum partials
__device__ float g_cs  [HH];                    // final column sums of h

// ---------------- SGEMM: C = A1@B1 (+ A2@B2) (+bias) (+relu) --------------
// A: row-major M x 512 (row stride 512). B: row-major 512 x N. C: M x N.
// Tile 128x128, BK=8, 256 threads, 8x8 per-thread micro-tile.
template <bool RELU>
__global__ void sgemm(const float* __restrict__ A1, const float* __restrict__ B1,
                      const float* __restrict__ A2, const float* __restrict__ B2,
                      const float* __restrict__ bias,
                      float* __restrict__ C, int M, int N)
{
    const int K = 512;
    __shared__ float As[8][132];
    __shared__ float Bs[8][132];

    const int tid = threadIdx.x;
    const int bm  = blockIdx.y * 128;
    const int bn  = blockIdx.x * 128;

    const int aRow = tid >> 1;          // 0..127
    const int aCol = (tid & 1) * 4;     // 0 or 4
    const int bRow = tid >> 5;          // 0..7
    const int bCol = (tid & 31) * 4;    // 0..124
    const int ty   = tid >> 4;          // 0..15  -> rows ty*8..ty*8+7
    const int tx   = tid & 15;          // 0..15  -> cols tx*8..tx*8+7

    float acc[8][8];
#pragma unroll
    for (int i = 0; i < 8; ++i)
#pragma unroll
        for (int j = 0; j < 8; ++j) acc[i][j] = 0.f;

    const int npass = (A2 != nullptr) ? 2 : 1;
    for (int p = 0; p < npass; ++p) {
        const float* __restrict__ A = p ? A2 : A1;
        const float* __restrict__ B = p ? B2 : B1;
        for (int k0 = 0; k0 < K; k0 += 8) {
            float4 av = make_float4(0.f, 0.f, 0.f, 0.f);
            if (bm + aRow < M)
                av = *(const float4*)(A + (size_t)(bm + aRow) * K + k0 + aCol);
            As[aCol + 0][aRow] = av.x;
            As[aCol + 1][aRow] = av.y;
            As[aCol + 2][aRow] = av.z;
            As[aCol + 3][aRow] = av.w;

            float4 bv = *(const float4*)(B + (size_t)(k0 + bRow) * N + bn + bCol);
            Bs[bRow][bCol + 0] = bv.x;
            Bs[bRow][bCol + 1] = bv.y;
            Bs[bRow][bCol + 2] = bv.z;
            Bs[bRow][bCol + 3] = bv.w;
            __syncthreads();

#pragma unroll
            for (int k = 0; k < 8; ++k) {
                float a[8], b[8];
#pragma unroll
                for (int i = 0; i < 8; ++i) a[i] = As[k][ty * 8 + i];
#pragma unroll
                for (int j = 0; j < 8; ++j) b[j] = Bs[k][tx * 8 + j];
#pragma unroll
                for (int i = 0; i < 8; ++i)
#pragma unroll
                    for (int j = 0; j < 8; ++j)
                        acc[i][j] += a[i] * b[j];
            }
            __syncthreads();
        }
    }

#pragma unroll
    for (int i = 0; i < 8; ++i) {
        int row = bm + ty * 8 + i;
        if (row >= M) continue;
#pragma unroll
        for (int j = 0; j < 8; ++j) {
            int col = bn + tx * 8 + j;
            float v = acc[i][j];
            if (bias) v += bias[col];
            if (RELU) v = v > 0.f ? v : 0.f;
            C[(size_t)row * N + col] = v;
        }
    }
}

// ---------------- small helpers ------------------------------------------
__device__ __forceinline__ float sigm(float x) { return 1.f / (1.f + expf(-x)); }

// h_sum[r][j] = sum over 4 children hidden rows (children are contiguous)
__global__ void hsum_kernel(const float* __restrict__ hid, float* __restrict__ out,
                            int n, int sc)
{
    int idx = blockIdx.x * blockDim.x + threadIdx.x;
    if (idx >= n * HH) return;
    int r = idx >> 9, j = idx & 511;
    const float* base = hid + (size_t)(sc + 4 * r) * HH + j;
    out[idx] = base[0] + base[HH] + base[2 * HH] + base[3 * HH];
}

// leaf cell: h_sum = ch = cc = 0
__global__ void leaf_pw(const float* __restrict__ iou,
                        const float* __restrict__ bix, const float* __restrict__ bih,
                        float* __restrict__ hid, float* __restrict__ cell)
{
    int idx = blockIdx.x * blockDim.x + threadIdx.x;
    if (idx >= NLEAF * HH) return;
    int r = idx >> 9, j = idx & 511;
    const float* row = iou + (size_t)r * 1536;
    float i = sigm (row[j]        + bix[j]        + bih[j]);
    float o = sigm (row[512 + j]  + bix[512 + j]  + bih[512 + j]);
    float u = tanhf(row[1024 + j] + bix[1024 + j] + bih[1024 + j]);
    float c = i * u;
    size_t g = (size_t)(SLEAF + r) * HH + j;
    cell[g] = c;
    hid[g]  = o * tanhf(c);
}

// internal cell: 4 children, all masked-in
__global__ void int_pw(const float* __restrict__ iou, const float* __restrict__ fx,
                       const float* __restrict__ fh,
                       const float* __restrict__ bix, const float* __restrict__ bih,
                       const float* __restrict__ bfx, const float* __restrict__ bfh,
                       float* __restrict__ hid, float* __restrict__ cell,
                       int n, int s, int sc)
{
    int idx = blockIdx.x * blockDim.x + threadIdx.x;
    if (idx >= n * HH) return;
    int r = idx >> 9, j = idx & 511;
    const float* row = iou + (size_t)r * 1536;
    float i = sigm (row[j]        + bix[j]        + bih[j]);
    float o = sigm (row[512 + j]  + bix[512 + j]  + bih[512 + j]);
    float u = tanhf(row[1024 + j] + bix[1024 + j] + bih[1024 + j]);
    float fxv = fx[(size_t)r * HH + j] + bfx[j] + bfh[j];
    float acc = i * u;
#pragma unroll
    for (int k = 0; k < 4; ++k) {
        float f = sigm(fxv + fh[(size_t)(4 * r + k) * HH + j]);
        acc += f * cell[(size_t)(sc + 4 * r + k) * HH + j];
    }
    size_t g = (size_t)(s + r) * HH + j;
    cell[g] = acc;
    hid[g]  = o * tanhf(acc);
}

// deterministic column-sum of h: stage 1 partials (512 blocks)
__global__ void colsum_part(const float* __restrict__ h, float* __restrict__ part)
{
    int b = blockIdx.x;
    const int rows_per = (NN + 511) / 512;  // 171
    int r0 = b * rows_per;
    int r1 = r0 + rows_per; if (r1 > NN) r1 = NN;
    for (int j = threadIdx.x; j < HH; j += blockDim.x) {
        float s = 0.f;
        for (int r = r0; r < r1; ++r) s += h[(size_t)r * HH + j];
        part[(size_t)b * HH + j] = s;
    }
}

__global__ void colsum_final(const float* __restrict__ part, float* __restrict__ cs)
{
    int j = blockIdx.x * blockDim.x + threadIdx.x;
    if (j >= HH) return;
    float acc = 0.f;
    for (int b = 0; b < 512; ++b) acc += part[(size_t)b * HH + j];
    cs[j] = acc;
}

// tree_emb[j] = (sum_rows h) . W_out[:,j] + N * b_out[j]
__global__ void tree_kernel(const float* __restrict__ cs, const float* __restrict__ W_out,
                            const float* __restrict__ b_out, float* __restrict__ out)
{
    int j = threadIdx.x;  // 256
    float acc = (float)NN * b_out[j];
    for (int k = 0; k < HH; ++k) acc += cs[k] * W_out[(size_t)k * OUTF + j];
    out[j] = acc;
}

// ---------------- driver ---------------------------------------------------
static float* sym(const void* s)
{
    void* p = nullptr;
    cudaGetSymbolAddress(&p, s);
    return (float*)p;
}

extern "C" void kernel_launch(void* const* d_in, const int* in_sizes, int n_in,
                              void* d_out, int out_size)
{
    (void)in_sizes; (void)n_in; (void)out_size;
    const float* x      = (const float*)d_in[0];
    const float* W_in   = (const float*)d_in[8];
    const float* b_in   = (const float*)d_in[9];
    const float* W_ioux = (const float*)d_in[10];  // (2, 512, 1536)
    const float* b_ioux = (const float*)d_in[11];  // (2, 1536)
    const float* W_iouh = (const float*)d_in[12];
    const float* b_iouh = (const float*)d_in[13];
    const float* W_fx   = (const float*)d_in[14];  // (2, 512, 512)
    const float* b_fx   = (const float*)d_in[15];  // (2, 512)
    const float* W_fh   = (const float*)d_in[16];
    const float* b_fh   = (const float*)d_in[17];
    const float* W_out  = (const float*)d_in[18];  // (512, 256)
    const float* b_out  = (const float*)d_in[19];  // (256)
    float* out = (float*)d_out;

    float* h0   = sym(g_h0);
    float* hid  = sym(g_hid);
    float* cell = sym(g_cell);
    float* iou  = sym(g_iou);
    float* hsm  = sym(g_hsum);
    float* fx   = sym(g_fx);
    float* fh   = sym(g_fh);
    float* part = sym(g_part);
    float* cs   = sym(g_cs);

    // input projection: h0 = relu(x @ W_in + b_in)
    sgemm<true><<<dim3(HH / 128, (NN + 127) / 128), 256>>>(
        x, W_in, nullptr, nullptr, b_in, h0, NN, HH);

    for (int l = 0; l < 2; ++l) {
        float* hin  = (l == 0) ? h0 : hid;
        float* hout = (l == 0) ? hid : h0;
        const float* Wix = W_ioux + (size_t)l * HH * 1536;
        const float* Wih = W_iouh + (size_t)l * HH * 1536;
        const float* Wfx = W_fx   + (size_t)l * HH * HH;
        const float* Wfh = W_fh   + (size_t)l * HH * HH;
        const float* Bix = b_ioux + (size_t)l * 1536;
        const float* Bih = b_iouh + (size_t)l * 1536;
        const float* Bfx = b_fx   + (size_t)l * HH;
        const float* Bfh = b_fh   + (size_t)l * HH;

        // ---- leaf level (d=8): no children
        sgemm<false><<<dim3(1536 / 128, NLEAF / 128), 256>>>(
            hin + (size_t)SLEAF * HH, Wix, nullptr, nullptr, nullptr, iou, NLEAF, 1536);
        leaf_pw<<<(NLEAF * HH) / 256, 256>>>(iou, Bix, Bih, hout, cell);

        // ---- internal levels d = 7..0
        for (int d = 7; d >= 0; --d) {
            int s  = LS[d];
            int n  = LS[d + 1] - LS[d];
            int sc = LS[d + 1];
            int nblk_pw = (n * HH + 255) / 256;

            hsum_kernel<<<nblk_pw, 256>>>(hout, hsm, n, sc);
            sgemm<false><<<dim3(1536 / 128, (n + 127) / 128), 256>>>(
                hin + (size_t)s * HH, Wix, hsm, Wih, nullptr, iou, n, 1536);
            sgemm<false><<<dim3(HH / 128, (n + 127) / 128), 256>>>(
                hin + (size_t)s * HH, Wfx, nullptr, nullptr, nullptr, fx, n, HH);
            sgemm<false><<<dim3(HH / 128, (4 * n + 127) / 128), 256>>>(
                hout + (size_t)sc * HH, Wfh, nullptr, nullptr, nullptr, fh, 4 * n, HH);
            int_pw<<<nblk_pw, 256>>>(iou, fx, fh, Bix, Bih, Bfx, Bfh,
                                     hout, cell, n, s, sc);
        }
    }

    // final h is in h0 (layer 1 wrote there)
    // node_emb = h0 @ W_out + b_out  -> out[0 : NN*OUTF]
    sgemm<false><<<dim3(OUTF / 128, (NN + 127) / 128), 256>>>(
        h0, W_out, nullptr, nullptr, b_out, out, NN, OUTF);

    // tree_emb = (sum_rows h0) @ W_out + NN * b_out -> out[NN*OUTF : +OUTF]
    colsum_part<<<512, 256>>>(h0, part);
    colsum_final<<<2, 256>>>(part, cs);
    tree_kernel<<<1, 256>>>(cs, W_out, b_out, out + (size_t)NN * OUTF);
}

// round 3
// speedup vs baseline: 2.1060x; 2.1060x over previous
#include <cuda_runtime.h>
#include <cuda_bf16.h>
#include <cstdint>
#include <math.h>

// ---------------- problem constants ----------------
#define NN     87381
#define HH     512
#define OUTF   256
#define NLEAF  65536
#define SLEAF  21845
static const int LS[10] = {0,1,5,21,85,341,1365,5461,21845,87381};

// converted weight offsets (elements), all [N,K=512] row-major bf16
#define OFF_WIN    0
#define OFF_IOUX0  262144
#define OFF_IOUX1  1048576
#define OFF_IOUH0  1835008
#define OFF_IOUH1  2621440
#define OFF_FX0    3407872
#define OFF_FX1    3670016
#define OFF_FH0    3932160
#define OFF_FH1    4194304
#define OFF_WOUT   4456448
#define WTOT       4587520

// ---------------- scratch (device globals; no allocation) ----------
__device__ __nv_bfloat16 g_wh[WTOT];
__device__ __nv_bfloat16 g_wl[WTOT];
__device__ float g_h0  [(size_t)NN * HH];
__device__ float g_hid [(size_t)NN * HH];
__device__ float g_cell[(size_t)NN * HH];
__device__ float g_iou [(size_t)NLEAF * 1536];
__device__ float g_hsum[(size_t)16384 * HH];
__device__ float g_fx  [(size_t)16384 * HH];
__device__ float g_fh  [(size_t)NLEAF * HH];
__device__ float g_part[(size_t)512 * HH];
__device__ float g_cs  [HH];

// ---------------- portable PTX helpers (sm_80+ only) ----------------
__device__ __forceinline__ void mma16816(float* c, const uint32_t* a, const uint32_t* b) {
    asm volatile(
        "mma.sync.aligned.m16n8k16.row.col.f32.bf16.bf16.f32 "
        "{%0,%1,%2,%3}, {%4,%5,%6,%7}, {%8,%9}, {%0,%1,%2,%3};"
        : "+f"(c[0]), "+f"(c[1]), "+f"(c[2]), "+f"(c[3])
        : "r"(a[0]), "r"(a[1]), "r"(a[2]), "r"(a[3]), "r"(b[0]), "r"(b[1]));
}
__device__ __forceinline__ void cp16(uint16_t* dst, const void* src) {
    uint32_t d = (uint32_t)__cvta_generic_to_shared(dst);
    asm volatile("cp.async.cg.shared.global [%0], [%1], 16;" :: "r"(d), "l"(src));
}
__device__ __forceinline__ void cp_commit() { asm volatile("cp.async.commit_group;" ::: "memory"); }
__device__ __forceinline__ void cp_wait0()  { asm volatile("cp.async.wait_group 0;"  ::: "memory"); }

// fp32x8 -> bf16 hi/lo packed uint4
__device__ __forceinline__ void cvt8(float4 v0, float4 v1, uint4& hi, uint4& lo) {
    float f[8] = {v0.x, v0.y, v0.z, v0.w, v1.x, v1.y, v1.z, v1.w};
    uint32_t h[8], l[8];
#pragma unroll
    for (int i = 0; i < 8; ++i) {
        __nv_bfloat16 hb = __float2bfloat16(f[i]);
        float r = f[i] - __bfloat162float(hb);
        __nv_bfloat16 lb = __float2bfloat16(r);
        h[i] = (uint32_t)*(uint16_t*)&hb;
        l[i] = (uint32_t)*(uint16_t*)&lb;
    }
    hi = make_uint4(h[0] | (h[1] << 16), h[2] | (h[3] << 16),
                    h[4] | (h[5] << 16), h[6] | (h[7] << 16));
    lo = make_uint4(l[0] | (l[1] << 16), l[2] | (l[3] << 16),
                    l[4] | (l[5] << 16), l[6] | (l[7] << 16));
}

// ---------------- mma.sync GEMM: C = [A1@B1^T (+ A2@B2^T)] (+bias)(+relu)
// A: M x 512 fp32 row-major. B (pre-split hi/lo): [Ntot][512] bf16 row-major
// (= W^T, so C = A @ W). 3-pass bf16 split: Ah*Bh + Ah*Bl + Al*Bh.
// CTA tile 128x128, 8 warps in 2(m) x 4(n), warp tile 64x32, K chunk 16.
// SMEM (dynamic, 49152 B): 2 stages x {Ah, Al, Bh, Bl}[128][24] bf16.
#define STRD   24         // padded row stride (elems) -> conflict-free frags
#define TSZ    3072       // 128*24 elems per tile
#define STGE   12288      // elems per stage (4 tiles)

template <bool RELU>
__global__ __launch_bounds__(256, 2) void gemm_mma(
    const float* __restrict__ A1,
    const __nv_bfloat16* __restrict__ Bh1, const __nv_bfloat16* __restrict__ Bl1,
    const float* __restrict__ A2,
    const __nv_bfloat16* __restrict__ Bh2, const __nv_bfloat16* __restrict__ Bl2,
    const float* __restrict__ bias,
    float* __restrict__ C, int M, int Ntot)
{
    extern __shared__ uint16_t sm16[];
    const int t    = threadIdx.x;
    const int lane = t & 31, wid = t >> 5;
    const int q = lane >> 2, p = lane & 3;
    const int wm = wid >> 2, wn = wid & 3;      // 2 x 4 warp grid
    const int bm = blockIdx.y * 128;
    const int bn = blockIdx.x * 128;

    // per-chunk staging mapping
    const int ar = t >> 1;            // A/B row 0..127
    const int ak = (t & 1) * 8;       // k offset 0 or 8

    const int npass = (A2 != nullptr) ? 2 : 1;
    const int CT = npass * 32;        // K=512 per pass, 16 per chunk

    float acc[4][4][4];
#pragma unroll
    for (int im = 0; im < 4; ++im)
#pragma unroll
        for (int in = 0; in < 4; ++in)
#pragma unroll
            for (int r = 0; r < 4; ++r) acc[im][in][r] = 0.f;

    // ---- prologue: stage chunk 0 into stage 0
    {
        const __nv_bfloat16* Bh = Bh1;
        const __nv_bfloat16* Bl = Bl1;
        cp16(sm16 + 2 * TSZ + ar * STRD + ak, Bh + (size_t)(bn + ar) * 512 + ak);
        cp16(sm16 + 3 * TSZ + ar * STRD + ak, Bl + (size_t)(bn + ar) * 512 + ak);
        cp_commit();
        float4 v0 = make_float4(0.f, 0.f, 0.f, 0.f), v1 = v0;
        if (bm + ar < M) {
            const float* ap = A1 + (size_t)(bm + ar) * 512 + ak;
            v0 = *(const float4*)ap;
            v1 = *(const float4*)(ap + 4);
        }
        uint4 hi, lo;
        cvt8(v0, v1, hi, lo);
        *(uint4*)(sm16 + 0 * TSZ + ar * STRD + ak) = hi;
        *(uint4*)(sm16 + 1 * TSZ + ar * STRD + ak) = lo;
        cp_wait0();
    }
    __syncthreads();

    for (int c = 0; c < CT; ++c) {
        const int s = c & 1, ns = s ^ 1;
        uint16_t* stg = sm16 + s * STGE;
        const bool hasnext = (c + 1 < CT);

        float4 v0, v1;
        if (hasnext) {
            const int nc = c + 1;
            const int pass = nc >> 5;
            const int k0 = (nc & 31) * 16;
            const __nv_bfloat16* Bh = pass ? Bh2 : Bh1;
            const __nv_bfloat16* Bl = pass ? Bl2 : Bl1;
            uint16_t* nstg = sm16 + ns * STGE;
            cp16(nstg + 2 * TSZ + ar * STRD + ak, Bh + (size_t)(bn + ar) * 512 + k0 + ak);
            cp16(nstg + 3 * TSZ + ar * STRD + ak, Bl + (size_t)(bn + ar) * 512 + k0 + ak);
            cp_commit();
            v0 = make_float4(0.f, 0.f, 0.f, 0.f); v1 = v0;
            if (bm + ar < M) {
                const float* A = pass ? A2 : A1;
                const float* ap = A + (size_t)(bm + ar) * 512 + k0 + ak;
                v0 = *(const float4*)ap;
                v1 = *(const float4*)(ap + 4);
            }
        }

        // ---- compute chunk c
        {
            const uint16_t* AH = stg;
            const uint16_t* AL = stg + TSZ;
            const uint16_t* BH = stg + 2 * TSZ;
            const uint16_t* BL = stg + 3 * TSZ;

            uint32_t ubh[4][2], ubl[4][2];
#pragma unroll
            for (int in = 0; in < 4; ++in) {
                int n0 = wn * 32 + in * 8;
                int off = (n0 + q) * STRD + 2 * p;
                ubh[in][0] = *(const uint32_t*)(BH + off);
                ubh[in][1] = *(const uint32_t*)(BH + off + 8);
                ubl[in][0] = *(const uint32_t*)(BL + off);
                ubl[in][1] = *(const uint32_t*)(BL + off + 8);
            }
#pragma unroll
            for (int im = 0; im < 4; ++im) {
                int r0 = wm * 64 + im * 16;
                int off = (r0 + q) * STRD + 2 * p;
                uint32_t ah[4], al[4];
                ah[0] = *(const uint32_t*)(AH + off);
                ah[1] = *(const uint32_t*)(AH + off + 8 * STRD);
                ah[2] = *(const uint32_t*)(AH + off + 8);
                ah[3] = *(const uint32_t*)(AH + off + 8 * STRD + 8);
                al[0] = *(const uint32_t*)(AL + off);
                al[1] = *(const uint32_t*)(AL + off + 8 * STRD);
                al[2] = *(const uint32_t*)(AL + off + 8);
                al[3] = *(const uint32_t*)(AL + off + 8 * STRD + 8);
#pragma unroll
                for (int in = 0; in < 4; ++in) {
                    mma16816(acc[im][in], ah, ubh[in]);
                    mma16816(acc[im][in], ah, ubl[in]);
                    mma16816(acc[im][in], al, ubh[in]);
                }
            }
        }

        if (hasnext) {
            uint16_t* nstg = sm16 + ns * STGE;
            uint4 hi, lo;
            cvt8(v0, v1, hi, lo);
            *(uint4*)(nstg + 0 * TSZ + ar * STRD + ak) = hi;
            *(uint4*)(nstg + 1 * TSZ + ar * STRD + ak) = lo;
            cp_wait0();
        }
        __syncthreads();
    }

    // ---- epilogue
#pragma unroll
    for (int im = 0; im < 4; ++im) {
#pragma unroll
        for (int in = 0; in < 4; ++in) {
            int row = bm + wm * 64 + im * 16 + q;
            int col = bn + wn * 32 + in * 8 + 2 * p;
            float b0 = 0.f, b1 = 0.f;
            if (bias) { b0 = bias[col]; b1 = bias[col + 1]; }
            float c0 = acc[im][in][0] + b0;
            float c1 = acc[im][in][1] + b1;
            float c2 = acc[im][in][2] + b0;
            float c3 = acc[im][in][3] + b1;
            if (RELU) {
                c0 = c0 > 0.f ? c0 : 0.f;  c1 = c1 > 0.f ? c1 : 0.f;
                c2 = c2 > 0.f ? c2 : 0.f;  c3 = c3 > 0.f ? c3 : 0.f;
            }
            if (row < M)
                *(float2*)&C[(size_t)row * Ntot + col] = make_float2(c0, c1);
            if (row + 8 < M)
                *(float2*)&C[(size_t)(row + 8) * Ntot + col] = make_float2(c2, c3);
        }
    }
}

// ---------------- weight transpose + hi/lo split --------------------------
// W: [512, Ncols] fp32 row-major -> T[h|l]: [Ncols, 512] bf16
__global__ void conv_w(const float* __restrict__ W,
                       __nv_bfloat16* __restrict__ Th, __nv_bfloat16* __restrict__ Tl,
                       int Ncols)
{
    int idx = blockIdx.x * blockDim.x + threadIdx.x;
    if (idx >= 512 * Ncols) return;
    int n = idx >> 9, k = idx & 511;
    float v = W[(size_t)k * Ncols + n];
    __nv_bfloat16 h = __float2bfloat16(v);
    Th[idx] = h;
    Tl[idx] = __float2bfloat16(v - __bfloat162float(h));
}

// ---------------- pointwise kernels ---------------------------------------
__device__ __forceinline__ float sigm(float x) { return 1.f / (1.f + expf(-x)); }

__global__ void hsum_kernel(const float* __restrict__ hid, float* __restrict__ out,
                            int n, int sc)
{
    int idx = blockIdx.x * blockDim.x + threadIdx.x;
    if (idx >= n * HH) return;
    int r = idx >> 9, j = idx & 511;
    const float* base = hid + (size_t)(sc + 4 * r) * HH + j;
    out[idx] = base[0] + base[HH] + base[2 * HH] + base[3 * HH];
}

__global__ void leaf_pw(const float* __restrict__ iou,
                        const float* __restrict__ bix, const float* __restrict__ bih,
                        float* __restrict__ hid, float* __restrict__ cell)
{
    int idx = blockIdx.x * blockDim.x + threadIdx.x;
    if (idx >= NLEAF * HH) return;
    int r = idx >> 9, j = idx & 511;
    const float* row = iou + (size_t)r * 1536;
    float i = sigm (row[j]        + bix[j]        + bih[j]);
    float o = sigm (row[512 + j]  + bix[512 + j]  + bih[512 + j]);
    float u = tanhf(row[1024 + j] + bix[1024 + j] + bih[1024 + j]);
    float c = i * u;
    size_t g = (size_t)(SLEAF + r) * HH + j;
    cell[g] = c;
    hid[g]  = o * tanhf(c);
}

__global__ void int_pw(const float* __restrict__ iou, const float* __restrict__ fx,
                       const float* __restrict__ fh,
                       const float* __restrict__ bix, const float* __restrict__ bih,
                       const float* __restrict__ bfx, const float* __restrict__ bfh,
                       float* __restrict__ hid, float* __restrict__ cell,
                       int n, int s, int sc)
{
    int idx = blockIdx.x * blockDim.x + threadIdx.x;
    if (idx >= n * HH) return;
    int r = idx >> 9, j = idx & 511;
    const float* row = iou + (size_t)r * 1536;
    float i = sigm (row[j]        + bix[j]        + bih[j]);
    float o = sigm (row[512 + j]  + bix[512 + j]  + bih[512 + j]);
    float u = tanhf(row[1024 + j] + bix[1024 + j] + bih[1024 + j]);
    float fxv = fx[(size_t)r * HH + j] + bfx[j] + bfh[j];
    float acc = i * u;
#pragma unroll
    for (int k = 0; k < 4; ++k) {
        float f = sigm(fxv + fh[(size_t)(4 * r + k) * HH + j]);
        acc += f * cell[(size_t)(sc + 4 * r + k) * HH + j];
    }
    size_t g = (size_t)(s + r) * HH + j;
    cell[g] = acc;
    hid[g]  = o * tanhf(acc);
}

__global__ void colsum_part(const float* __restrict__ h, float* __restrict__ part)
{
    int b = blockIdx.x;
    const int rows_per = (NN + 511) / 512;
    int r0 = b * rows_per;
    int r1 = r0 + rows_per; if (r1 > NN) r1 = NN;
    for (int j = threadIdx.x; j < HH; j += blockDim.x) {
        float s = 0.f;
        for (int r = r0; r < r1; ++r) s += h[(size_t)r * HH + j];
        part[(size_t)b * HH + j] = s;
    }
}

__global__ void colsum_final(const float* __restrict__ part, float* __restrict__ cs)
{
    int j = blockIdx.x * blockDim.x + threadIdx.x;
    if (j >= HH) return;
    float acc = 0.f;
    for (int b = 0; b < 512; ++b) acc += part[(size_t)b * HH + j];
    cs[j] = acc;
}

__global__ void tree_kernel(const float* __restrict__ cs, const float* __restrict__ W_out,
                            const float* __restrict__ b_out, float* __restrict__ out)
{
    int j = threadIdx.x;
    float acc = (float)NN * b_out[j];
    for (int k = 0; k < HH; ++k) acc += cs[k] * W_out[(size_t)k * OUTF + j];
    out[j] = acc;
}

// ---------------- driver ---------------------------------------------------
static void* symv(const void* s) { void* p = nullptr; cudaGetSymbolAddress(&p, s); return p; }

extern "C" void kernel_launch(void* const* d_in, const int* in_sizes, int n_in,
                              void* d_out, int out_size)
{
    (void)in_sizes; (void)n_in; (void)out_size;
    const float* x      = (const float*)d_in[0];
    const float* W_in   = (const float*)d_in[8];
    const float* b_in   = (const float*)d_in[9];
    const float* W_ioux = (const float*)d_in[10];
    const float* b_ioux = (const float*)d_in[11];
    const float* W_iouh = (const float*)d_in[12];
    const float* b_iouh = (const float*)d_in[13];
    const float* W_fx   = (const float*)d_in[14];
    const float* b_fx   = (const float*)d_in[15];
    const float* W_fh   = (const float*)d_in[16];
    const float* b_fh   = (const float*)d_in[17];
    const float* W_out  = (const float*)d_in[18];
    const float* b_out  = (const float*)d_in[19];
    float* out = (float*)d_out;

    float* h0   = (float*)symv(g_h0);
    float* hid  = (float*)symv(g_hid);
    float* cell = (float*)symv(g_cell);
    float* iou  = (float*)symv(g_iou);
    float* hsm  = (float*)symv(g_hsum);
    float* fx   = (float*)symv(g_fx);
    float* fh   = (float*)symv(g_fh);
    float* part = (float*)symv(g_part);
    float* cs   = (float*)symv(g_cs);
    __nv_bfloat16* wh = (__nv_bfloat16*)symv(g_wh);
    __nv_bfloat16* wl = (__nv_bfloat16*)symv(g_wl);

    const int SMB = 49152;
    cudaFuncSetAttribute(gemm_mma<false>, cudaFuncAttributeMaxDynamicSharedMemorySize, SMB);
    cudaFuncSetAttribute(gemm_mma<true>,  cudaFuncAttributeMaxDynamicSharedMemorySize, SMB);

    // ---- weight conversion (transpose + bf16 hi/lo split)
    conv_w<<<(512 * 512 + 255) / 256, 256>>>(W_in, wh + OFF_WIN, wl + OFF_WIN, 512);
    conv_w<<<(512 * 1536 + 255) / 256, 256>>>(W_ioux,              wh + OFF_IOUX0, wl + OFF_IOUX0, 1536);
    conv_w<<<(512 * 1536 + 255) / 256, 256>>>(W_ioux + 512 * 1536, wh + OFF_IOUX1, wl + OFF_IOUX1, 1536);
    conv_w<<<(512 * 1536 + 255) / 256, 256>>>(W_iouh,              wh + OFF_IOUH0, wl + OFF_IOUH0, 1536);
    conv_w<<<(512 * 1536 + 255) / 256, 256>>>(W_iouh + 512 * 1536, wh + OFF_IOUH1, wl + OFF_IOUH1, 1536);
    conv_w<<<(512 * 512 + 255) / 256, 256>>>(W_fx,             wh + OFF_FX0, wl + OFF_FX0, 512);
    conv_w<<<(512 * 512 + 255) / 256, 256>>>(W_fx + 512 * 512, wh + OFF_FX1, wl + OFF_FX1, 512);
    conv_w<<<(512 * 512 + 255) / 256, 256>>>(W_fh,             wh + OFF_FH0, wl + OFF_FH0, 512);
    conv_w<<<(512 * 512 + 255) / 256, 256>>>(W_fh + 512 * 512, wh + OFF_FH1, wl + OFF_FH1, 512);
    conv_w<<<(512 * 256 + 255) / 256, 256>>>(W_out, wh + OFF_WOUT, wl + OFF_WOUT, 256);

    const int MT_ALL = (NN + 127) / 128;   // 683

    // ---- input projection: h0 = relu(x @ W_in + b_in)
    gemm_mma<true><<<dim3(4, MT_ALL), 256, SMB>>>(
        x, wh + OFF_WIN, wl + OFF_WIN, nullptr, nullptr, nullptr, b_in, h0, NN, HH);

    const int offX[2] = {OFF_IOUX0, OFF_IOUX1};
    const int offH[2] = {OFF_IOUH0, OFF_IOUH1};
    const int offF[2] = {OFF_FX0, OFF_FX1};
    const int offG[2] = {OFF_FH0, OFF_FH1};

    for (int l = 0; l < 2; ++l) {
        float* hin  = (l == 0) ? h0 : hid;
        float* hout = (l == 0) ? hid : h0;
        const float* Bix = b_ioux + (size_t)l * 1536;
        const float* Bih = b_iouh + (size_t)l * 1536;
        const float* Bfx = b_fx   + (size_t)l * HH;
        const float* Bfh = b_fh   + (size_t)l * HH;

        // leaf level
        gemm_mma<false><<<dim3(12, NLEAF / 128), 256, SMB>>>(
            hin + (size_t)SLEAF * HH, wh + offX[l], wl + offX[l],
            nullptr, nullptr, nullptr, nullptr, iou, NLEAF, 1536);
        leaf_pw<<<(NLEAF * HH) / 256, 256>>>(iou, Bix, Bih, hout, cell);

        for (int d = 7; d >= 0; --d) {
            int s  = LS[d];
            int n  = LS[d + 1] - LS[d];
            int sc = LS[d + 1];
            int mt  = (n + 127) / 128;
            int mt4 = (4 * n + 127) / 128;
            int nblk_pw = (n * HH + 255) / 256;

            hsum_kernel<<<nblk_pw, 256>>>(hout, hsm, n, sc);
            gemm_mma<false><<<dim3(12, mt), 256, SMB>>>(
                hin + (size_t)s * HH, wh + offX[l], wl + offX[l],
                hsm, wh + offH[l], wl + offH[l], nullptr, iou, n, 1536);
            gemm_mma<false><<<dim3(4, mt), 256, SMB>>>(
                hin + (size_t)s * HH, wh + offF[l], wl + offF[l],
                nullptr, nullptr, nullptr, nullptr, fx, n, HH);
            gemm_mma<false><<<dim3(4, mt4), 256, SMB>>>(
                hout + (size_t)sc * HH, wh + offG[l], wl + offG[l],
                nullptr, nullptr, nullptr, nullptr, fh, 4 * n, HH);
            int_pw<<<nblk_pw, 256>>>(iou, fx, fh, Bix, Bih, Bfx, Bfh,
                                     hout, cell, n, s, sc);
        }
    }

    // node_emb = h0 @ W_out + b_out
    gemm_mma<false><<<dim3(2, MT_ALL), 256, SMB>>>(
        h0, wh + OFF_WOUT, wl + OFF_WOUT, nullptr, nullptr, nullptr,
        b_out, out, NN, OUTF);

    // tree_emb
    colsum_part<<<512, 256>>>(h0, part);
    colsum_final<<<2, 256>>>(part, cs);
    tree_kernel<<<1, 256>>>(cs, W_out, b_out, out + (size_t)NN * OUTF);
}